// round 6
// baseline (speedup 1.0000x reference)
#include <cuda_runtime.h>
#include <cuda_bf16.h>
#include <cstdint>

// Problem constants (fixed by the dataset)
#define DHEAD 128   // d
#define MPROJ 128   // m (projection dim)
#define NQ    4096  // queries
#define NK    8192  // keys
#define SCALE_CONST 0.009791516698f  // sqrt(pi/2)/128 (fp32)

// ---------------- device-global scratch (no runtime allocation) ----------------
__device__ __nv_bfloat16 g_signs[NK * MPROJ];   // signs, ±1 in bf16, [key][m]
__device__ float         g_nscale[NK];          // ||r_k|| * sqrt(pi/2)/m
__device__ __nv_bfloat16 g_qhi[NQ * MPROJ];     // hi part of q_proj
__device__ __nv_bfloat16 g_qlo[NQ * MPROJ];     // lo part of q_proj

// ================================================================================
// Prep kernel: fp32 GEMM row_block @ S^T  (64 rows per block, full 128x128 S in smem)
//   blocks [0, 128): residual rows -> signs (bf16 +-1) + nscale
//   blocks [128,192): query rows   -> q_proj split into bf16 hi/lo
// ================================================================================
#define PREP_ROWS 64
#define PREP_THREADS 256
#define PADP 129
#define PREP_SMEM_BYTES ((PREP_ROWS * PADP + MPROJ * PADP) * 4)

__global__ __launch_bounds__(PREP_THREADS)
void qjl_prep_kernel(const float* __restrict__ query,
                     const float* __restrict__ residual,
                     const float* __restrict__ S)
{
    extern __shared__ float smf[];
    float* Ash = smf;                       // [64][129]
    float* Ssh = smf + PREP_ROWS * PADP;    // [128][129]

    const int tid = threadIdx.x;
    const bool is_res = (blockIdx.x < (NK / PREP_ROWS));
    const int rbase = is_res ? blockIdx.x * PREP_ROWS
                             : (blockIdx.x - NK / PREP_ROWS) * PREP_ROWS;
    const float* src = is_res ? residual : query;

    // ---- fill row tile (64 x 128 floats) ----
    const float4* gA = (const float4*)(src + (size_t)rbase * DHEAD);
    #pragma unroll
    for (int idx = tid; idx < PREP_ROWS * (DHEAD / 4); idx += PREP_THREADS) {
        int r = idx >> 5, c4 = idx & 31;
        float4 v = gA[idx];
        float* d = Ash + r * PADP + c4 * 4;
        d[0] = v.x; d[1] = v.y; d[2] = v.z; d[3] = v.w;
    }
    // ---- fill S (128 x 128 floats) ----
    const float4* gS = (const float4*)S;
    #pragma unroll
    for (int idx = tid; idx < MPROJ * (DHEAD / 4); idx += PREP_THREADS) {
        int r = idx >> 5, c4 = idx & 31;
        float4 v = gS[idx];
        float* d = Ssh + r * PADP + c4 * 4;
        d[0] = v.x; d[1] = v.y; d[2] = v.z; d[3] = v.w;
    }
    __syncthreads();

    // ---- norms (residual blocks only) ----
    if (is_res && tid < PREP_ROWS) {
        float s = 0.f;
        #pragma unroll 8
        for (int k = 0; k < DHEAD; k++) {
            float a = Ash[tid * PADP + k];
            s += a * a;
        }
        g_nscale[rbase + tid] = sqrtf(s) * SCALE_CONST;
    }

    // ---- register-tiled fp32 GEMM: each thread -> 4 rows x 8 cols ----
    const int rg = tid & 15;   // row group: rows 4*rg .. 4*rg+3
    const int cg = tid >> 4;   // col group: cols 8*cg .. 8*cg+7 (broadcast within warp)

    float acc[4][8];
    #pragma unroll
    for (int i = 0; i < 4; i++)
        #pragma unroll
        for (int j = 0; j < 8; j++) acc[i][j] = 0.f;

    #pragma unroll 4
    for (int k = 0; k < DHEAD; k++) {
        float a[4], b[8];
        #pragma unroll
        for (int i = 0; i < 4; i++) a[i] = Ash[(4 * rg + i) * PADP + k];
        #pragma unroll
        for (int j = 0; j < 8; j++) b[j] = Ssh[(8 * cg + j) * PADP + k];
        #pragma unroll
        for (int i = 0; i < 4; i++)
            #pragma unroll
            for (int j = 0; j < 8; j++)
                acc[i][j] = fmaf(a[i], b[j], acc[i][j]);
    }

    if (is_res) {
        #pragma unroll
        for (int i = 0; i < 4; i++) {
            union { __nv_bfloat16 h[8]; uint4 u; } pk;
            #pragma unroll
            for (int j = 0; j < 8; j++)
                pk.h[j] = __float2bfloat16(acc[i][j] >= 0.f ? 1.f : -1.f);
            int row = rbase + 4 * rg + i;
            *(uint4*)(g_signs + (size_t)row * MPROJ + 8 * cg) = pk.u;
        }
    } else {
        #pragma unroll
        for (int i = 0; i < 4; i++) {
            union { __nv_bfloat16 h[8]; uint4 u; } ph, pl;
            #pragma unroll
            for (int j = 0; j < 8; j++) {
                float x = acc[i][j];
                __nv_bfloat16 hb = __float2bfloat16(x);
                ph.h[j] = hb;
                pl.h[j] = __float2bfloat16(x - __bfloat162float(hb));
            }
            int row = rbase + 4 * rg + i;
            *(uint4*)(g_qhi + (size_t)row * MPROJ + 8 * cg) = ph.u;
            *(uint4*)(g_qlo + (size_t)row * MPROJ + 8 * cg) = pl.u;
        }
    }
}

// ================================================================================
// Main GEMM: out[q][k] = nscale[k] * sum_m (qhi+qlo)[q][m] * signs[k][m]
// CTA tile 128x128, full K=128. 8 warps, each 64x32. mma.sync m16n8k16 bf16.
// ================================================================================
#define MT 256
#define PADB 136   // bf16 elements per smem row (272 bytes -> conflict-free ldmatrix)
#define MAIN_SMEM_BYTES (3 * 128 * PADB * 2 + 128 * 4)

__device__ __forceinline__ uint32_t smem_u32(const void* p) {
    return (uint32_t)__cvta_generic_to_shared(p);
}

__device__ __forceinline__ void ldm_x4(uint32_t* r, uint32_t addr) {
    asm volatile("ldmatrix.sync.aligned.m8n8.x4.shared.b16 {%0,%1,%2,%3}, [%4];"
                 : "=r"(r[0]), "=r"(r[1]), "=r"(r[2]), "=r"(r[3])
                 : "r"(addr));
}

__device__ __forceinline__ void mma_bf16(float* d, const uint32_t* a,
                                         uint32_t b0, uint32_t b1) {
    asm volatile(
        "mma.sync.aligned.m16n8k16.row.col.f32.bf16.bf16.f32 "
        "{%0,%1,%2,%3}, {%4,%5,%6,%7}, {%8,%9}, {%0,%1,%2,%3};"
        : "+f"(d[0]), "+f"(d[1]), "+f"(d[2]), "+f"(d[3])
        : "r"(a[0]), "r"(a[1]), "r"(a[2]), "r"(a[3]), "r"(b0), "r"(b1));
}

__global__ __launch_bounds__(MT, 2)
void qjl_mma_kernel(float* __restrict__ out)
{
    extern __shared__ __nv_bfloat16 smb[];
    __nv_bfloat16* Ah = smb;                    // [128][136]
    __nv_bfloat16* Al = Ah + 128 * PADB;        // [128][136]
    __nv_bfloat16* Bs = Al + 128 * PADB;        // [128][136]
    float* nsc = (float*)(Bs + 128 * PADB);     // [128]

    const int tid = threadIdx.x;
    const int qtile = blockIdx.y * 128;
    const int ktile = blockIdx.x * 128;

    // ---- fill smem tiles (each 128 rows x 16 uint4) ----
    const uint4* gAh = (const uint4*)(g_qhi   + (size_t)qtile * MPROJ);
    const uint4* gAl = (const uint4*)(g_qlo   + (size_t)qtile * MPROJ);
    const uint4* gB  = (const uint4*)(g_signs + (size_t)ktile * MPROJ);
    #pragma unroll
    for (int idx = tid; idx < 128 * 16; idx += MT) {
        int r = idx >> 4, c = idx & 15;
        ((uint4*)(Ah + r * PADB))[c] = gAh[idx];
        ((uint4*)(Al + r * PADB))[c] = gAl[idx];
        ((uint4*)(Bs + r * PADB))[c] = gB[idx];
    }
    if (tid < 128) nsc[tid] = g_nscale[ktile + tid];
    __syncthreads();

    const int warp = tid >> 5, lane = tid & 31;
    const int wm = warp >> 2;        // 0..1  (M)
    const int wn = warp & 3;         // 0..3  (N)
    const int lr = lane & 15;        // ldmatrix row
    const int lcol = (lane >> 4) * 8;// ldmatrix col group (in bf16 elems)

    float acc[4][4][4];
    #pragma unroll
    for (int i = 0; i < 4; i++)
        #pragma unroll
        for (int j = 0; j < 4; j++)
            #pragma unroll
            for (int t = 0; t < 4; t++) acc[i][j][t] = 0.f;

    #pragma unroll
    for (int ks = 0; ks < 8; ks++) {
        const int kc = ks * 16 + lcol;
        uint32_t ah[4][4], al[4][4], bb[2][4];
        #pragma unroll
        for (int i = 0; i < 4; i++) {
            int row = wm * 64 + i * 16 + lr;
            ldm_x4(ah[i], smem_u32(Ah + row * PADB + kc));
            ldm_x4(al[i], smem_u32(Al + row * PADB + kc));
        }
        #pragma unroll
        for (int jj = 0; jj < 2; jj++) {
            int row = wn * 32 + jj * 16 + lr;
            ldm_x4(bb[jj], smem_u32(Bs + row * PADB + kc));
        }
        #pragma unroll
        for (int i = 0; i < 4; i++) {
            #pragma unroll
            for (int j = 0; j < 4; j++) {
                uint32_t b0 = bb[j >> 1][j & 1];
                uint32_t b1 = bb[j >> 1][(j & 1) + 2];
                mma_bf16(acc[i][j], ah[i], b0, b1);
                mma_bf16(acc[i][j], al[i], b0, b1);
            }
        }
    }

    // ---- epilogue: scale by nscale[col] and store ----
    #pragma unroll
    for (int i = 0; i < 4; i++) {
        #pragma unroll
        for (int j = 0; j < 4; j++) {
            int r0 = qtile + wm * 64 + i * 16 + (lane >> 2);
            int cl = wn * 32 + j * 8 + 2 * (lane & 3);
            int c = ktile + cl;
            float s0 = nsc[cl], s1 = nsc[cl + 1];
            float2 v0 = make_float2(acc[i][j][0] * s0, acc[i][j][1] * s1);
            float2 v1 = make_float2(acc[i][j][2] * s0, acc[i][j][3] * s1);
            *(float2*)(out + (size_t)r0 * NK + c) = v0;
            *(float2*)(out + (size_t)(r0 + 8) * NK + c) = v1;
        }
    }
}

// ================================================================================
extern "C" void kernel_launch(void* const* d_in, const int* in_sizes, int n_in,
                              void* d_out, int out_size)
{
    const float* query    = (const float*)d_in[0];
    const float* residual = (const float*)d_in[1];
    const float* S        = (const float*)d_in[2];
    float* out = (float*)d_out;

    cudaFuncSetAttribute(qjl_prep_kernel,
                         cudaFuncAttributeMaxDynamicSharedMemorySize,
                         PREP_SMEM_BYTES);
    cudaFuncSetAttribute(qjl_mma_kernel,
                         cudaFuncAttributeMaxDynamicSharedMemorySize,
                         MAIN_SMEM_BYTES);

    // 128 residual blocks + 64 query blocks
    qjl_prep_kernel<<<(NK + NQ) / PREP_ROWS, PREP_THREADS, PREP_SMEM_BYTES>>>(
        query, residual, S);

    // 64 key-tiles x 32 query-tiles
    qjl_mma_kernel<<<dim3(NK / 128, NQ / 128), MT, MAIN_SMEM_BYTES>>>(out);
}